// round 4
// baseline (speedup 1.0000x reference)
#include <cuda_runtime.h>
#include <cstdint>
#include <math.h>

#define NN 50000
#define DD 200
#define RR 480
#define TT 4
#define EE 100000
#define SLOPE 0.22916666666666666f

// ---------------- device scratch (no allocations) ----------------
__device__ float g_h[NN * DD];
__device__ float g_hhA[NN * DD];
__device__ float g_hhB[NN * DD];
__device__ float g_agg[NN * DD];
__device__ float g_norm[NN];          // row scale for time gate
__device__ float g_h0[RR * DD];
__device__ float g_ssum[RR * DD];
__device__ float g_cnt[RR];
__device__ float g_Bt[5 * DD * DD + 4096];  // transposed weights + OOB pad
// CSR scratch
__device__ int g_cnt_i[NN];
__device__ int g_off[NN + 1];
__device__ int g_wcnt[NN];
__device__ int g_esrc[EE];
__device__ int g_eet[EE];

// ---------------- helpers ----------------
__device__ __forceinline__ uint32_t smem_u32(const void* p) {
    uint32_t a;
    asm("{ .reg .u64 t; cvta.to.shared.u64 t, %1; cvt.u32.u64 %0, t; }" : "=r"(a) : "l"(p));
    return a;
}

#define CP16(sm_addr, gptr) \
    asm volatile("cp.async.ca.shared.global [%0], [%1], 16;" :: "r"(sm_addr), "l"(gptr))
#define CP_COMMIT() asm volatile("cp.async.commit_group;" ::: "memory")
#define CP_WAIT1()  asm volatile("cp.async.wait_group 1;" ::: "memory")
#define CP_WAIT0()  asm volatile("cp.async.wait_group 0;" ::: "memory")

#define MMA_TF32(d, a, b0, b1)                                                    \
    asm volatile("mma.sync.aligned.m16n8k8.row.col.f32.tf32.tf32.f32 "            \
                 "{%0,%1,%2,%3}, {%4,%5,%6,%7}, {%8,%9}, {%0,%1,%2,%3};"          \
                 : "+f"((d)[0]), "+f"((d)[1]), "+f"((d)[2]), "+f"((d)[3])         \
                 : "r"((a)[0]), "r"((a)[1]), "r"((a)[2]), "r"((a)[3]),            \
                   "r"(b0), "r"(b1))

__device__ __forceinline__ void red_add_v4(float* p, float4 v) {
    asm volatile("red.global.add.v4.f32 [%0], {%1, %2, %3, %4};"
                 :: "l"(p), "f"(v.x), "f"(v.y), "f"(v.z), "f"(v.w) : "memory");
}

// ---------------- fused tensor-core GEMM (mma.sync tf32) ----------------
// acc[128,200] = sum_parts Apart @ Bpart^T.
// mode 0: out = rrelu(acc). mode 1: tw=sigmoid(acc+bt);
//         cur = curv*scalev[row]; h = tw*cur + (1-tw)*h; hist = h.
__global__ void __launch_bounds__(256)
k_mma_gemm(const float* __restrict__ A0, const float* __restrict__ A1,
           const float* __restrict__ B0g, const float* __restrict__ B1g,
           const float* __restrict__ scalev, float* __restrict__ outp,
           const float* __restrict__ bt, const float* __restrict__ curv,
           float* __restrict__ hstate, float* __restrict__ hist,
           int mode, int nparts) {
    __shared__ __align__(16) float sm[2][4032];  // 1536 A + 2496 B per stage
    int tid = threadIdx.x, lane = tid & 31, wid = tid >> 5;
    int wr = wid >> 1, wc = wid & 1;
    int row0 = blockIdx.x * 128;

    float acc[2][13][4];
    #pragma unroll
    for (int mt = 0; mt < 2; ++mt)
        #pragma unroll
        for (int nt = 0; nt < 13; ++nt)
            #pragma unroll
            for (int q = 0; q < 4; ++q) acc[mt][nt][q] = 0.f;

    const int nk = nparts * 25;

    auto issue = [&](int c) {
        const float* A = (c < 25) ? A0 : A1;
        const float* B = (c < 25) ? B0g : B1g;
        int k0 = ((c < 25) ? c : c - 25) * 8;
        int buf = c & 1;
        {
            int r = tid >> 1, h = tid & 1;
            int row = row0 + r;
            if (row >= NN) row = NN - 1;
            uint32_t sa = smem_u32(&sm[buf][r * 12 + h * 4]);
            CP16(sa, A + (size_t)row * DD + k0 + h * 4);
        }
        #pragma unroll
        for (int j = tid; j < 416; j += 256) {
            int n = j >> 1, h = j & 1;
            uint32_t sb = smem_u32(&sm[buf][1536 + n * 12 + h * 4]);
            CP16(sb, B + (size_t)n * DD + k0 + h * 4);
        }
        CP_COMMIT();
    };

    issue(0);
    for (int c = 0; c < nk; ++c) {
        if (c + 1 < nk) { issue(c + 1); CP_WAIT1(); } else { CP_WAIT0(); }
        __syncthreads();
        int buf = c & 1;
        uint32_t a[2][4];
        int rb = wr * 32 + (lane >> 2);
        int kk = lane & 3;
        #pragma unroll
        for (int mt = 0; mt < 2; ++mt) {
            int r = rb + mt * 16;
            a[mt][0] = __float_as_uint(sm[buf][r * 12 + kk]);
            a[mt][1] = __float_as_uint(sm[buf][(r + 8) * 12 + kk]);
            a[mt][2] = __float_as_uint(sm[buf][r * 12 + kk + 4]);
            a[mt][3] = __float_as_uint(sm[buf][(r + 8) * 12 + kk + 4]);
        }
        int nb = wc * 104 + (lane >> 2);
        #pragma unroll
        for (int nt = 0; nt < 13; ++nt) {
            int n = nb + nt * 8;
            uint32_t b0 = __float_as_uint(sm[buf][1536 + n * 12 + kk]);
            uint32_t b1 = __float_as_uint(sm[buf][1536 + n * 12 + kk + 4]);
            MMA_TF32(acc[0][nt], a[0], b0, b1);
            MMA_TF32(acc[1][nt], a[1], b0, b1);
        }
        __syncthreads();
    }

    // ---- epilogue ----
    #pragma unroll
    for (int mt = 0; mt < 2; ++mt) {
        int r = row0 + wr * 32 + mt * 16 + (lane >> 2);
        #pragma unroll
        for (int nt = 0; nt < 13; ++nt) {
            int col = wc * 104 + nt * 8 + (lane & 3) * 2;
            if (col >= DD) continue;
            #pragma unroll
            for (int half = 0; half < 2; ++half) {
                int row = r + half * 8;
                if (row >= NN) continue;
                float v0 = acc[mt][nt][half * 2];
                float v1 = acc[mt][nt][half * 2 + 1];
                size_t off = (size_t)row * DD + col;
                if (mode == 0) {
                    float2 o;
                    o.x = (v0 >= 0.f) ? v0 : v0 * SLOPE;
                    o.y = (v1 >= 0.f) ? v1 : v1 * SLOPE;
                    *(float2*)&outp[off] = o;
                } else {
                    float sc = scalev[row];
                    float t0 = 1.f / (1.f + expf(-(v0 + bt[col])));
                    float t1 = 1.f / (1.f + expf(-(v1 + bt[col + 1])));
                    float2 cu = *(const float2*)&curv[off];
                    float2 ho = *(const float2*)&hstate[off];
                    float2 hn;
                    hn.x = t0 * (cu.x * sc) + (1.f - t0) * ho.x;
                    hn.y = t1 * (cu.y * sc) + (1.f - t1) * ho.y;
                    *(float2*)&hstate[off] = hn;
                    *(float2*)&hist[off] = hn;
                }
            }
        }
    }
}

// ---------------- CSR build ----------------
__global__ void k_count(const int* __restrict__ dst) {
    int e = blockIdx.x * blockDim.x + threadIdx.x;
    if (e < EE) atomicAdd(&g_cnt_i[dst[e]], 1);
}

__global__ void __launch_bounds__(1024) k_scan() {
    __shared__ int sT[1024];
    const int per = (NN + 1023) / 1024;  // 49
    int tid = threadIdx.x;
    int base = tid * per;
    int tot = 0;
    for (int k = 0; k < per; ++k) {
        int i = base + k;
        if (i < NN) tot += g_cnt_i[i];
    }
    sT[tid] = tot;
    __syncthreads();
    // inclusive Hillis-Steele
    for (int o = 1; o < 1024; o <<= 1) {
        int v = (tid >= o) ? sT[tid - o] : 0;
        __syncthreads();
        sT[tid] += v;
        __syncthreads();
    }
    int run = (tid == 0) ? 0 : sT[tid - 1];
    for (int k = 0; k < per; ++k) {
        int i = base + k;
        if (i < NN) {
            g_off[i] = run;
            run += g_cnt_i[i];
        }
    }
    if (tid == 1023) g_off[NN] = EE;
}

__global__ void k_fill(const int* __restrict__ src, const int* __restrict__ dst,
                       const int* __restrict__ et) {
    int e = blockIdx.x * blockDim.x + threadIdx.x;
    if (e >= EE) return;
    int d_ = dst[e];
    int pos = g_off[d_] + atomicAdd(&g_wcnt[d_], 1);
    g_esrc[pos] = src[e];
    g_eet[pos] = et[e];
}

// ---------------- CSR gather-aggregate (norm folded) ----------------
// outA[n] = (1/max(deg,1)) * sum_{e: dst=n} (hh[src_e] + h0[et_e])
__global__ void __launch_bounds__(256)
k_agg_csr(const float* __restrict__ hh, float* __restrict__ outA) {
    int row = blockIdx.x * 8 + (threadIdx.x >> 5);
    int lane = threadIdx.x & 31;
    if (row >= NN) return;
    int beg = g_off[row], end = g_off[row + 1];
    float4 a0 = make_float4(0.f, 0.f, 0.f, 0.f);
    float4 a1 = a0;
    for (int j = beg; j < end; ++j) {
        int s = g_esrc[j], r = g_eet[j];
        const float4* hs = (const float4*)(hh + (size_t)s * DD);
        const float4* h0 = (const float4*)(g_h0 + (size_t)r * DD);
        float4 x = hs[lane], y = h0[lane];
        a0.x += x.x + y.x; a0.y += x.y + y.y;
        a0.z += x.z + y.z; a0.w += x.w + y.w;
        if (lane < 18) {
            float4 u = hs[lane + 32], v = h0[lane + 32];
            a1.x += u.x + v.x; a1.y += u.y + v.y;
            a1.z += u.z + v.z; a1.w += u.w + v.w;
        }
    }
    float nrm = 1.f / fmaxf((float)(end - beg), 1.f);
    a0.x *= nrm; a0.y *= nrm; a0.z *= nrm; a0.w *= nrm;
    float4* po = (float4*)(outA + (size_t)row * DD);
    po[lane] = a0;
    if (lane < 18) {
        a1.x *= nrm; a1.y *= nrm; a1.z *= nrm; a1.w *= nrm;
        po[lane + 32] = a1;
    }
}

// ---------------- utility kernels ----------------
__global__ void k_copy(const float* __restrict__ in, float* __restrict__ out, int n) {
    int i = blockIdx.x * blockDim.x + threadIdx.x;
    if (i < n) out[i] = in[i];
}
__global__ void k_transpose(const float* __restrict__ W, float* __restrict__ Bt) {
    int idx = blockIdx.x * blockDim.x + threadIdx.x;
    if (idx < DD * DD) {
        int k = idx / DD, n = idx - k * DD;
        Bt[n * DD + k] = W[idx];
    }
}
__global__ void k_l2norm_rows(const float* __restrict__ in, float* __restrict__ out, int nrows) {
    int w = (blockIdx.x * blockDim.x + threadIdx.x) >> 5;
    int lane = threadIdx.x & 31;
    if (w >= nrows) return;
    const float* r = in + (size_t)w * DD;
    float ss = 0.f;
    for (int d = lane; d < DD; d += 32) { float v = r[d]; ss += v * v; }
    #pragma unroll
    for (int o = 16; o; o >>= 1) ss += __shfl_xor_sync(0xffffffffu, ss, o);
    float s = 1.f / fmaxf(sqrtf(ss), 1e-12f);
    float* po = out + (size_t)w * DD;
    for (int d = lane; d < DD; d += 32) po[d] = r[d] * s;
}
// scale only: sc[row] = 1/max(||row||, 1e-12)
__global__ void k_l2scale(const float* __restrict__ in, float* __restrict__ sc, int nrows) {
    int w = (blockIdx.x * blockDim.x + threadIdx.x) >> 5;
    int lane = threadIdx.x & 31;
    if (w >= nrows) return;
    const float* r = in + (size_t)w * DD;
    float ss = 0.f;
    for (int d = lane; d < DD; d += 32) { float v = r[d]; ss += v * v; }
    #pragma unroll
    for (int o = 16; o; o >>= 1) ss += __shfl_xor_sync(0xffffffffu, ss, o);
    if (lane == 0) sc[w] = 1.f / fmaxf(sqrtf(ss), 1e-12f);
}

// ssum[et] += h[src] + h[dst] (v4 reductions); cnt[et] += 2
__global__ void k_rel_scatter(const int* __restrict__ src, const int* __restrict__ dst,
                              const int* __restrict__ et) {
    int idx = blockIdx.x * blockDim.x + threadIdx.x;
    if (idx >= EE * 50) return;
    int e = idx / 50, q = idx - e * 50;
    int s = src[e], d_ = dst[e], r = et[e];
    float4 a = *(const float4*)&g_h[(size_t)s * DD + q * 4];
    float4 b = *(const float4*)&g_h[(size_t)d_ * DD + q * 4];
    float4 v = make_float4(a.x + b.x, a.y + b.y, a.z + b.z, a.w + b.w);
    red_add_v4(&g_ssum[(size_t)r * DD + q * 4], v);
    if (q == 0) atomicAdd(&g_cnt[r], 2.f);
}

// ---------------- GRU (warp-per-output-row) ----------------
__global__ void k_gru(const float* __restrict__ emb_rel, const float* __restrict__ W_ih,
                      const float* __restrict__ W_hh, const float* __restrict__ b_ih,
                      const float* __restrict__ b_hh) {
    __shared__ float sx[2 * DD];
    __shared__ float shp[DD];
    __shared__ float sgi[3 * DD];
    __shared__ float sgh[3 * DD];
    __shared__ float shn[DD];
    __shared__ float sred[8];
    int r = blockIdx.x, tid = threadIdx.x, lane = tid & 31, wid = tid >> 5;
    float inv_cnt = 1.f / fmaxf(g_cnt[r], 1.f);
    for (int d = tid; d < DD; d += 256) {
        sx[d] = emb_rel[r * DD + d];
        sx[DD + d] = g_ssum[r * DD + d] * inv_cnt;
        shp[d] = g_h0[r * DD + d];
    }
    __syncthreads();
    for (int j = wid; j < 3 * DD; j += 8) {
        const float* wi = W_ih + (size_t)j * (2 * DD);
        float a = 0.f;
        for (int k = lane; k < 2 * DD; k += 32) a = fmaf(sx[k], wi[k], a);
        const float* wh = W_hh + (size_t)j * DD;
        float b = 0.f;
        for (int k = lane; k < DD; k += 32) b = fmaf(shp[k], wh[k], b);
        #pragma unroll
        for (int o = 16; o; o >>= 1) {
            a += __shfl_xor_sync(0xffffffffu, a, o);
            b += __shfl_xor_sync(0xffffffffu, b, o);
        }
        if (lane == 0) { sgi[j] = a + b_ih[j]; sgh[j] = b + b_hh[j]; }
    }
    __syncthreads();
    float ss = 0.f;
    for (int d = tid; d < DD; d += 256) {
        float rg = 1.f / (1.f + expf(-(sgi[d] + sgh[d])));
        float zg = 1.f / (1.f + expf(-(sgi[DD + d] + sgh[DD + d])));
        float ng = tanhf(sgi[2 * DD + d] + rg * sgh[2 * DD + d]);
        float hn = (1.f - zg) * ng + zg * shp[d];
        shn[d] = hn;
        ss += hn * hn;
    }
    #pragma unroll
    for (int o = 16; o; o >>= 1) ss += __shfl_xor_sync(0xffffffffu, ss, o);
    if (lane == 0) sred[wid] = ss;
    __syncthreads();
    if (tid == 0) {
        float t = 0.f;
        #pragma unroll
        for (int i = 0; i < 8; ++i) t += sred[i];
        sred[0] = t;
    }
    __syncthreads();
    float s = 1.f / fmaxf(sqrtf(sred[0]), 1e-12f);
    for (int d = tid; d < DD; d += 256) g_h0[r * DD + d] = shn[d] * s;
}

// ---------------- host driver ----------------
extern "C" void kernel_launch(void* const* d_in, const int* in_sizes, int n_in,
                              void* d_out, int out_size) {
    const int* src = (const int*)d_in[0];
    const int* dst = (const int*)d_in[1];
    const int* et  = (const int*)d_in[2];
    const float* dyn     = (const float*)d_in[3];
    const float* emb_rel = (const float*)d_in[4];
    const float* W_ih    = (const float*)d_in[5];
    const float* W_hh    = (const float*)d_in[6];
    const float* b_ih    = (const float*)d_in[7];
    const float* b_hh    = (const float*)d_in[8];
    const float* W_nb    = (const float*)d_in[9];
    const float* W_lp    = (const float*)d_in[10];
    const float* Wt      = (const float*)d_in[11];
    const float* bt      = (const float*)d_in[12];
    float* out = (float*)d_out;

    float *p_h, *p_hhA, *p_hhB, *p_agg, *p_norm, *p_h0, *p_ssum, *p_cnt, *p_Bt;
    int *p_cnt_i, *p_wcnt;
    cudaGetSymbolAddress((void**)&p_h,     g_h);
    cudaGetSymbolAddress((void**)&p_hhA,   g_hhA);
    cudaGetSymbolAddress((void**)&p_hhB,   g_hhB);
    cudaGetSymbolAddress((void**)&p_agg,   g_agg);
    cudaGetSymbolAddress((void**)&p_norm,  g_norm);
    cudaGetSymbolAddress((void**)&p_h0,    g_h0);
    cudaGetSymbolAddress((void**)&p_ssum,  g_ssum);
    cudaGetSymbolAddress((void**)&p_cnt,   g_cnt);
    cudaGetSymbolAddress((void**)&p_Bt,    g_Bt);
    cudaGetSymbolAddress((void**)&p_cnt_i, g_cnt_i);
    cudaGetSymbolAddress((void**)&p_wcnt,  g_wcnt);

    const int gemm_blocks = (NN + 127) / 128;  // 391
    const int tb = (DD * DD + 255) / 256;
    const int eb = (EE * 50 + 255) / 256;
    const int agg_blocks = (NN + 7) / 8;       // 6250

    // transposed weights: [0]=Wn0^T [1]=Wl0^T [2]=Wn1^T [3]=Wl1^T [4]=Wt^T
    k_transpose<<<tb, 256>>>(W_nb,           p_Bt + 0 * DD * DD);
    k_transpose<<<tb, 256>>>(W_lp,           p_Bt + 1 * DD * DD);
    k_transpose<<<tb, 256>>>(W_nb + DD * DD, p_Bt + 2 * DD * DD);
    k_transpose<<<tb, 256>>>(W_lp + DD * DD, p_Bt + 3 * DD * DD);
    k_transpose<<<tb, 256>>>(Wt,             p_Bt + 4 * DD * DD);

    // init: h = l2norm(dynamic_emb); h0 = emb_rel
    k_l2norm_rows<<<(NN * 32 + 255) / 256, 256>>>(dyn, p_h, NN);
    k_copy<<<(RR * DD + 255) / 256, 256>>>(emb_rel, p_h0, RR * DD);

    for (int t = 0; t < TT; ++t) {
        const int* s_t = src + t * EE;
        const int* d_t = dst + t * EE;
        const int* e_t = et  + t * EE;

        // relation mean + GRU update of h0
        cudaMemsetAsync(p_ssum, 0, RR * DD * sizeof(float));
        cudaMemsetAsync(p_cnt,  0, RR * sizeof(float));
        k_rel_scatter<<<eb, 256>>>(s_t, d_t, e_t);
        k_gru<<<RR, 256>>>(emb_rel, W_ih, W_hh, b_ih, b_hh);

        // CSR build (by dst)
        cudaMemsetAsync(p_cnt_i, 0, NN * sizeof(int));
        cudaMemsetAsync(p_wcnt,  0, NN * sizeof(int));
        k_count<<<(EE + 255) / 256, 256>>>(d_t);
        k_scan<<<1, 1024>>>();
        k_fill<<<(EE + 255) / 256, 256>>>(s_t, d_t, e_t);

        // layer 0: h -> hhA
        k_agg_csr<<<agg_blocks, 256>>>(p_h, p_agg);
        k_mma_gemm<<<gemm_blocks, 256>>>(
            p_agg, p_h, p_Bt + 0 * DD * DD, p_Bt + 1 * DD * DD, nullptr,
            p_hhA, nullptr, nullptr, nullptr, nullptr, 0, 2);

        // layer 1: hhA -> hhB
        k_agg_csr<<<agg_blocks, 256>>>(p_hhA, p_agg);
        k_mma_gemm<<<gemm_blocks, 256>>>(
            p_agg, p_hhA, p_Bt + 2 * DD * DD, p_Bt + 3 * DD * DD, nullptr,
            p_hhB, nullptr, nullptr, nullptr, nullptr, 0, 2);

        // row scales of hhB (cur = hhB * scale in the epilogue)
        k_l2scale<<<(NN * 32 + 255) / 256, 256>>>(p_hhB, p_norm, NN);

        // time gate
        k_mma_gemm<<<gemm_blocks, 256>>>(
            p_h, nullptr, p_Bt + 4 * DD * DD, nullptr, p_norm,
            nullptr, bt, p_hhB, p_h, out + (size_t)t * NN * DD, 1, 1);
    }
}

// round 5
// speedup vs baseline: 1.0982x; 1.0982x over previous
#include <cuda_runtime.h>
#include <cstdint>
#include <math.h>

#define NN 50000
#define DD 200
#define RR 480
#define TT 4
#define EE 100000
#define SLOPE 0.22916666666666666f

// ---------------- device scratch (no allocations) ----------------
__device__ float g_h[NN * DD];
__device__ float g_hhA[NN * DD];
__device__ float g_hhB[NN * DD];
__device__ float g_agg[NN * DD];
__device__ float g_norm[NN];          // 1/max(deg,1)
__device__ float g_ssq[NN];           // row sum-of-squares of hhB
__device__ float g_h0[RR * DD];
__device__ float g_Bt[5 * DD * DD + 4096];  // transposed weights + OOB pad
// relation CSR scratch
__device__ int g_rcnt[RR];
__device__ int g_rwc[RR];
__device__ int g_roff[RR + 1];
__device__ int g_rlist[2 * EE];

// ---------------- helpers ----------------
__device__ __forceinline__ uint32_t smem_u32(const void* p) {
    uint32_t a;
    asm("{ .reg .u64 t; cvta.to.shared.u64 t, %1; cvt.u32.u64 %0, t; }" : "=r"(a) : "l"(p));
    return a;
}

#define CP16(sm_addr, gptr) \
    asm volatile("cp.async.ca.shared.global [%0], [%1], 16;" :: "r"(sm_addr), "l"(gptr))
#define CP_COMMIT() asm volatile("cp.async.commit_group;" ::: "memory")
#define CP_WAIT1()  asm volatile("cp.async.wait_group 1;" ::: "memory")
#define CP_WAIT0()  asm volatile("cp.async.wait_group 0;" ::: "memory")

#define MMA_TF32(d, a, b0, b1)                                                    \
    asm volatile("mma.sync.aligned.m16n8k8.row.col.f32.tf32.tf32.f32 "            \
                 "{%0,%1,%2,%3}, {%4,%5,%6,%7}, {%8,%9}, {%0,%1,%2,%3};"          \
                 : "+f"((d)[0]), "+f"((d)[1]), "+f"((d)[2]), "+f"((d)[3])         \
                 : "r"((a)[0]), "r"((a)[1]), "r"((a)[2]), "r"((a)[3]),            \
                   "r"(b0), "r"(b1))

__device__ __forceinline__ void red_add_v4(float* p, float4 v) {
    asm volatile("red.global.add.v4.f32 [%0], {%1, %2, %3, %4};"
                 :: "l"(p), "f"(v.x), "f"(v.y), "f"(v.z), "f"(v.w) : "memory");
}

// ---------------- fused tensor-core GEMM (mma.sync tf32) ----------------
// acc[128,200] = sum_parts Apart @ Bpart^T; norm row-scale after part 0.
// mode 0: out = rrelu(acc); optional ssqout[row] += sum(out^2).
// mode 1: tw=sigmoid(acc+bt); sc=1/max(sqrt(ssq[row]),eps);
//         h = tw*(curv*sc) + (1-tw)*h; hist = h.
__global__ void __launch_bounds__(256)
k_mma_gemm(const float* __restrict__ A0, const float* __restrict__ A1,
           const float* __restrict__ B0g, const float* __restrict__ B1g,
           const float* __restrict__ normv, float* __restrict__ outp,
           float* __restrict__ ssqout,
           const float* __restrict__ bt, const float* __restrict__ curv,
           const float* __restrict__ ssqv,
           float* __restrict__ hstate, float* __restrict__ hist,
           int mode, int nparts) {
    __shared__ __align__(16) float sm[2][4032];  // 1536 A + 2496 B per stage
    int tid = threadIdx.x, lane = tid & 31, wid = tid >> 5;
    int wr = wid >> 1, wc = wid & 1;
    int row0 = blockIdx.x * 128;

    float acc[2][13][4];
    #pragma unroll
    for (int mt = 0; mt < 2; ++mt)
        #pragma unroll
        for (int nt = 0; nt < 13; ++nt)
            #pragma unroll
            for (int q = 0; q < 4; ++q) acc[mt][nt][q] = 0.f;

    const int nk = nparts * 25;

    auto issue = [&](int c) {
        const float* A = (c < 25) ? A0 : A1;
        const float* B = (c < 25) ? B0g : B1g;
        int k0 = ((c < 25) ? c : c - 25) * 8;
        int buf = c & 1;
        {
            int r = tid >> 1, h = tid & 1;
            int row = row0 + r;
            if (row >= NN) row = NN - 1;
            uint32_t sa = smem_u32(&sm[buf][r * 12 + h * 4]);
            CP16(sa, A + (size_t)row * DD + k0 + h * 4);
        }
        #pragma unroll
        for (int j = tid; j < 416; j += 256) {
            int n = j >> 1, h = j & 1;
            uint32_t sb = smem_u32(&sm[buf][1536 + n * 12 + h * 4]);
            CP16(sb, B + (size_t)n * DD + k0 + h * 4);
        }
        CP_COMMIT();
    };

    issue(0);
    for (int c = 0; c < nk; ++c) {
        if (c + 1 < nk) { issue(c + 1); CP_WAIT1(); } else { CP_WAIT0(); }
        __syncthreads();
        int buf = c & 1;
        uint32_t a[2][4];
        int rb = wr * 32 + (lane >> 2);
        int kk = lane & 3;
        #pragma unroll
        for (int mt = 0; mt < 2; ++mt) {
            int r = rb + mt * 16;
            a[mt][0] = __float_as_uint(sm[buf][r * 12 + kk]);
            a[mt][1] = __float_as_uint(sm[buf][(r + 8) * 12 + kk]);
            a[mt][2] = __float_as_uint(sm[buf][r * 12 + kk + 4]);
            a[mt][3] = __float_as_uint(sm[buf][(r + 8) * 12 + kk + 4]);
        }
        int nb = wc * 104 + (lane >> 2);
        #pragma unroll
        for (int nt = 0; nt < 13; ++nt) {
            int n = nb + nt * 8;
            uint32_t b0 = __float_as_uint(sm[buf][1536 + n * 12 + kk]);
            uint32_t b1 = __float_as_uint(sm[buf][1536 + n * 12 + kk + 4]);
            MMA_TF32(acc[0][nt], a[0], b0, b1);
            MMA_TF32(acc[1][nt], a[1], b0, b1);
        }
        // end of part 0: apply per-row deg-norm to accumulators
        if (c == 24 && nparts == 2 && normv != nullptr) {
            #pragma unroll
            for (int mt = 0; mt < 2; ++mt) {
                int r = row0 + wr * 32 + mt * 16 + (lane >> 2);
                int r2 = r + 8;
                float n0 = normv[r < NN ? r : NN - 1];
                float n1 = normv[r2 < NN ? r2 : NN - 1];
                #pragma unroll
                for (int nt = 0; nt < 13; ++nt) {
                    acc[mt][nt][0] *= n0; acc[mt][nt][1] *= n0;
                    acc[mt][nt][2] *= n1; acc[mt][nt][3] *= n1;
                }
            }
        }
        __syncthreads();
    }

    // ---- epilogue ----
    float sq[2][2] = {{0.f, 0.f}, {0.f, 0.f}};
    #pragma unroll
    for (int mt = 0; mt < 2; ++mt) {
        int r = row0 + wr * 32 + mt * 16 + (lane >> 2);
        #pragma unroll
        for (int nt = 0; nt < 13; ++nt) {
            int col = wc * 104 + nt * 8 + (lane & 3) * 2;
            if (col >= DD) continue;
            #pragma unroll
            for (int half = 0; half < 2; ++half) {
                int row = r + half * 8;
                if (row >= NN) continue;
                float v0 = acc[mt][nt][half * 2];
                float v1 = acc[mt][nt][half * 2 + 1];
                size_t off = (size_t)row * DD + col;
                if (mode == 0) {
                    float2 o;
                    o.x = (v0 >= 0.f) ? v0 : v0 * SLOPE;
                    o.y = (v1 >= 0.f) ? v1 : v1 * SLOPE;
                    *(float2*)&outp[off] = o;
                    sq[mt][half] += o.x * o.x + o.y * o.y;
                } else {
                    float sc = 1.f / fmaxf(sqrtf(ssqv[row]), 1e-12f);
                    float t0 = 1.f / (1.f + expf(-(v0 + bt[col])));
                    float t1 = 1.f / (1.f + expf(-(v1 + bt[col + 1])));
                    float2 cu = *(const float2*)&curv[off];
                    float2 ho = *(const float2*)&hstate[off];
                    float2 hn;
                    hn.x = t0 * (cu.x * sc) + (1.f - t0) * ho.x;
                    hn.y = t1 * (cu.y * sc) + (1.f - t1) * ho.y;
                    *(float2*)&hstate[off] = hn;
                    *(float2*)&hist[off] = hn;
                }
            }
        }
    }
    if (mode == 0 && ssqout != nullptr) {
        #pragma unroll
        for (int mt = 0; mt < 2; ++mt)
            #pragma unroll
            for (int half = 0; half < 2; ++half) {
                float v = sq[mt][half];
                v += __shfl_xor_sync(0xffffffffu, v, 1);
                v += __shfl_xor_sync(0xffffffffu, v, 2);
                int row = row0 + wr * 32 + mt * 16 + (lane >> 2) + half * 8;
                if ((lane & 3) == 0 && row < NN) atomicAdd(&ssqout[row], v);
            }
    }
}

// ---------------- relation CSR build ----------------
__global__ void k_rcount(const int* __restrict__ et) {
    int e = blockIdx.x * blockDim.x + threadIdx.x;
    if (e < EE) atomicAdd(&g_rcnt[et[e]], 2);
}
__global__ void __launch_bounds__(512) k_rscan() {
    __shared__ int s[512];
    int tid = threadIdx.x;
    int v = (tid < RR) ? g_rcnt[tid] : 0;
    s[tid] = v;
    __syncthreads();
    for (int o = 1; o < 512; o <<= 1) {
        int u = (tid >= o) ? s[tid - o] : 0;
        __syncthreads();
        s[tid] += u;
        __syncthreads();
    }
    if (tid < RR) g_roff[tid] = s[tid] - v;  // exclusive
    if (tid == 0) g_roff[RR] = 2 * EE;
}
__global__ void k_rfill(const int* __restrict__ src, const int* __restrict__ dst,
                        const int* __restrict__ et) {
    int e = blockIdx.x * blockDim.x + threadIdx.x;
    if (e >= EE) return;
    int r = et[e];
    int pos = g_roff[r] + atomicAdd(&g_rwc[r], 2);
    g_rlist[pos] = src[e];
    g_rlist[pos + 1] = dst[e];
}

// ---------------- GRU fused with relation-mean gather ----------------
__global__ void __launch_bounds__(256)
k_gru(const float* __restrict__ emb_rel, const float* __restrict__ W_ih,
      const float* __restrict__ W_hh, const float* __restrict__ b_ih,
      const float* __restrict__ b_hh) {
    __shared__ float sx[2 * DD];
    __shared__ float shp[DD];
    __shared__ __align__(16) float part[8 * DD];
    __shared__ float sgi[3 * DD];
    __shared__ float sgh[3 * DD];
    __shared__ float shn[DD];
    __shared__ float sred[8];
    int r = blockIdx.x, tid = threadIdx.x, lane = tid & 31, wid = tid >> 5;
    int beg = g_roff[r], end = g_roff[r + 1];

    // gather x_mean = mean over entity rows touching relation r
    float4 a0 = make_float4(0.f, 0.f, 0.f, 0.f);
    float4 a1 = a0;
    for (int j = beg + wid; j < end; j += 8) {
        int ent = g_rlist[j];
        const float4* hs = (const float4*)(g_h + (size_t)ent * DD);
        float4 x = hs[lane];
        a0.x += x.x; a0.y += x.y; a0.z += x.z; a0.w += x.w;
        if (lane < 18) {
            float4 u = hs[lane + 32];
            a1.x += u.x; a1.y += u.y; a1.z += u.z; a1.w += u.w;
        }
    }
    float4* pw = (float4*)(part + wid * DD);
    pw[lane] = a0;
    if (lane < 18) pw[lane + 32] = a1;

    for (int d = tid; d < DD; d += 256) {
        sx[d] = emb_rel[r * DD + d];
        shp[d] = g_h0[r * DD + d];
    }
    __syncthreads();
    float inv_cnt = 1.f / fmaxf((float)(end - beg), 1.f);
    for (int d = tid; d < DD; d += 256) {
        float s = 0.f;
        #pragma unroll
        for (int w = 0; w < 8; ++w) s += part[w * DD + d];
        sx[DD + d] = s * inv_cnt;
    }
    __syncthreads();

    for (int j = wid; j < 3 * DD; j += 8) {
        const float* wi = W_ih + (size_t)j * (2 * DD);
        float a = 0.f;
        for (int k = lane; k < 2 * DD; k += 32) a = fmaf(sx[k], wi[k], a);
        const float* wh = W_hh + (size_t)j * DD;
        float b = 0.f;
        for (int k = lane; k < DD; k += 32) b = fmaf(shp[k], wh[k], b);
        #pragma unroll
        for (int o = 16; o; o >>= 1) {
            a += __shfl_xor_sync(0xffffffffu, a, o);
            b += __shfl_xor_sync(0xffffffffu, b, o);
        }
        if (lane == 0) { sgi[j] = a + b_ih[j]; sgh[j] = b + b_hh[j]; }
    }
    __syncthreads();
    float ss = 0.f;
    for (int d = tid; d < DD; d += 256) {
        float rg = 1.f / (1.f + expf(-(sgi[d] + sgh[d])));
        float zg = 1.f / (1.f + expf(-(sgi[DD + d] + sgh[DD + d])));
        float ng = tanhf(sgi[2 * DD + d] + rg * sgh[2 * DD + d]);
        float hn = (1.f - zg) * ng + zg * shp[d];
        shn[d] = hn;
        ss += hn * hn;
    }
    #pragma unroll
    for (int o = 16; o; o >>= 1) ss += __shfl_xor_sync(0xffffffffu, ss, o);
    if (lane == 0) sred[wid] = ss;
    __syncthreads();
    if (tid == 0) {
        float t = 0.f;
        #pragma unroll
        for (int i = 0; i < 8; ++i) t += sred[i];
        sred[0] = t;
    }
    __syncthreads();
    float s = 1.f / fmaxf(sqrtf(sred[0]), 1e-12f);
    for (int d = tid; d < DD; d += 256) g_h0[r * DD + d] = shn[d] * s;
}

// ---------------- entity-side kernels ----------------
__global__ void k_deg(const int* __restrict__ dst) {
    int e = blockIdx.x * blockDim.x + threadIdx.x;
    if (e < EE) atomicAdd(&g_norm[dst[e]], 1.f);
}
__global__ void k_degnorm() {
    int i = blockIdx.x * blockDim.x + threadIdx.x;
    if (i < NN) g_norm[i] = 1.f / fmaxf(g_norm[i], 1.f);
}

// agg[dst] += hh[src] + h0[et]
__global__ void k_edge(const int* __restrict__ src, const int* __restrict__ dst,
                       const int* __restrict__ et, const float* __restrict__ hh) {
    int idx = blockIdx.x * blockDim.x + threadIdx.x;
    if (idx >= EE * 50) return;
    int e = idx / 50, q = idx - e * 50;
    int s = src[e], dn = dst[e], r = et[e];
    float4 a = *(const float4*)&hh[(size_t)s * DD + q * 4];
    float4 b = *(const float4*)&g_h0[(size_t)r * DD + q * 4];
    float4 v = make_float4(a.x + b.x, a.y + b.y, a.z + b.z, a.w + b.w);
    red_add_v4(&g_agg[(size_t)dn * DD + q * 4], v);
}

// ---------------- utility kernels ----------------
__global__ void k_copy(const float* __restrict__ in, float* __restrict__ out, int n) {
    int i = blockIdx.x * blockDim.x + threadIdx.x;
    if (i < n) out[i] = in[i];
}
__global__ void k_transpose(const float* __restrict__ W, float* __restrict__ Bt) {
    int idx = blockIdx.x * blockDim.x + threadIdx.x;
    if (idx < DD * DD) {
        int k = idx / DD, n = idx - k * DD;
        Bt[n * DD + k] = W[idx];
    }
}
__global__ void k_l2norm_rows(const float* __restrict__ in, float* __restrict__ out, int nrows) {
    int w = (blockIdx.x * blockDim.x + threadIdx.x) >> 5;
    int lane = threadIdx.x & 31;
    if (w >= nrows) return;
    const float* r = in + (size_t)w * DD;
    float ss = 0.f;
    for (int d = lane; d < DD; d += 32) { float v = r[d]; ss += v * v; }
    #pragma unroll
    for (int o = 16; o; o >>= 1) ss += __shfl_xor_sync(0xffffffffu, ss, o);
    float s = 1.f / fmaxf(sqrtf(ss), 1e-12f);
    float* po = out + (size_t)w * DD;
    for (int d = lane; d < DD; d += 32) po[d] = r[d] * s;
}

// ---------------- host driver ----------------
extern "C" void kernel_launch(void* const* d_in, const int* in_sizes, int n_in,
                              void* d_out, int out_size) {
    const int* src = (const int*)d_in[0];
    const int* dst = (const int*)d_in[1];
    const int* et  = (const int*)d_in[2];
    const float* dyn     = (const float*)d_in[3];
    const float* emb_rel = (const float*)d_in[4];
    const float* W_ih    = (const float*)d_in[5];
    const float* W_hh    = (const float*)d_in[6];
    const float* b_ih    = (const float*)d_in[7];
    const float* b_hh    = (const float*)d_in[8];
    const float* W_nb    = (const float*)d_in[9];
    const float* W_lp    = (const float*)d_in[10];
    const float* Wt      = (const float*)d_in[11];
    const float* bt      = (const float*)d_in[12];
    float* out = (float*)d_out;

    float *p_h, *p_hhA, *p_hhB, *p_agg, *p_norm, *p_ssq, *p_h0, *p_Bt;
    int *p_rcnt, *p_rwc;
    cudaGetSymbolAddress((void**)&p_h,    g_h);
    cudaGetSymbolAddress((void**)&p_hhA,  g_hhA);
    cudaGetSymbolAddress((void**)&p_hhB,  g_hhB);
    cudaGetSymbolAddress((void**)&p_agg,  g_agg);
    cudaGetSymbolAddress((void**)&p_norm, g_norm);
    cudaGetSymbolAddress((void**)&p_ssq,  g_ssq);
    cudaGetSymbolAddress((void**)&p_h0,   g_h0);
    cudaGetSymbolAddress((void**)&p_Bt,   g_Bt);
    cudaGetSymbolAddress((void**)&p_rcnt, g_rcnt);
    cudaGetSymbolAddress((void**)&p_rwc,  g_rwc);

    const int gemm_blocks = (NN + 127) / 128;  // 391
    const int tb = (DD * DD + 255) / 256;
    const int eb = (EE * 50 + 255) / 256;
    const int e1 = (EE + 255) / 256;

    // transposed weights: [0]=Wn0^T [1]=Wl0^T [2]=Wn1^T [3]=Wl1^T [4]=Wt^T
    k_transpose<<<tb, 256>>>(W_nb,           p_Bt + 0 * DD * DD);
    k_transpose<<<tb, 256>>>(W_lp,           p_Bt + 1 * DD * DD);
    k_transpose<<<tb, 256>>>(W_nb + DD * DD, p_Bt + 2 * DD * DD);
    k_transpose<<<tb, 256>>>(W_lp + DD * DD, p_Bt + 3 * DD * DD);
    k_transpose<<<tb, 256>>>(Wt,             p_Bt + 4 * DD * DD);

    // init: h = l2norm(dynamic_emb); h0 = emb_rel
    k_l2norm_rows<<<(NN * 32 + 255) / 256, 256>>>(dyn, p_h, NN);
    k_copy<<<(RR * DD + 255) / 256, 256>>>(emb_rel, p_h0, RR * DD);

    for (int t = 0; t < TT; ++t) {
        const int* s_t = src + t * EE;
        const int* d_t = dst + t * EE;
        const int* e_t = et  + t * EE;

        // relation CSR + fused GRU (updates h0)
        cudaMemsetAsync(p_rcnt, 0, RR * sizeof(int));
        cudaMemsetAsync(p_rwc,  0, RR * sizeof(int));
        k_rcount<<<e1, 256>>>(e_t);
        k_rscan<<<1, 512>>>();
        k_rfill<<<e1, 256>>>(s_t, d_t, e_t);
        k_gru<<<RR, 256>>>(emb_rel, W_ih, W_hh, b_ih, b_hh);

        // degrees -> norm
        cudaMemsetAsync(p_norm, 0, NN * sizeof(float));
        k_deg<<<e1, 256>>>(d_t);
        k_degnorm<<<(NN + 255) / 256, 256>>>();

        // layer 0: h -> hhA
        cudaMemsetAsync(p_agg, 0, (size_t)NN * DD * sizeof(float));
        k_edge<<<eb, 256>>>(s_t, d_t, e_t, p_h);
        k_mma_gemm<<<gemm_blocks, 256>>>(
            p_agg, p_h, p_Bt + 0 * DD * DD, p_Bt + 1 * DD * DD, p_norm,
            p_hhA, nullptr, nullptr, nullptr, nullptr, nullptr, nullptr, 0, 2);

        // layer 1: hhA -> hhB (+ fused row ssq)
        cudaMemsetAsync(p_agg, 0, (size_t)NN * DD * sizeof(float));
        cudaMemsetAsync(p_ssq, 0, NN * sizeof(float));
        k_edge<<<eb, 256>>>(s_t, d_t, e_t, p_hhA);
        k_mma_gemm<<<gemm_blocks, 256>>>(
            p_agg, p_hhA, p_Bt + 2 * DD * DD, p_Bt + 3 * DD * DD, p_norm,
            p_hhB, p_ssq, nullptr, nullptr, nullptr, nullptr, nullptr, 0, 2);

        // time gate: h = sigmoid(h@Wt+bt)*(hhB*rsqrt(ssq)) + (1-..)*h; hist = h
        k_mma_gemm<<<gemm_blocks, 256>>>(
            p_h, nullptr, p_Bt + 4 * DD * DD, nullptr, nullptr,
            nullptr, nullptr, bt, p_hhB, p_ssq, p_h, out + (size_t)t * NN * DD, 1, 1);
    }
}

// round 6
// speedup vs baseline: 1.1265x; 1.0257x over previous
#include <cuda_runtime.h>
#include <cstdint>
#include <math.h>

#define NN 50000
#define DD 200
#define RR 480
#define TT 4
#define EE 100000
#define SLOPE 0.22916666666666666f

// ---------------- device scratch (no allocations) ----------------
__device__ float g_h[NN * DD];
__device__ float g_hhA[NN * DD];
__device__ float g_hhB[NN * DD];
__device__ float g_agg[NN * DD];
__device__ float g_ssq[NN];
__device__ float g_h0[RR * DD];
__device__ float g_Bt[5 * DD * DD + 4096];  // transposed weights + OOB pad
// int scratch: [0,RR)=rcnt  [RR,2RR)=rwc  [2RR,2RR+NN)=deg(float bits)
__device__ int g_iblk[2 * RR + NN];
__device__ int g_roff[RR + 1];
__device__ int g_rlist[2 * EE];

// ---------------- helpers ----------------
__device__ __forceinline__ uint32_t smem_u32(const void* p) {
    uint32_t a;
    asm("{ .reg .u64 t; cvta.to.shared.u64 t, %1; cvt.u32.u64 %0, t; }" : "=r"(a) : "l"(p));
    return a;
}

#define CP16(sm_addr, gptr) \
    asm volatile("cp.async.ca.shared.global [%0], [%1], 16;" :: "r"(sm_addr), "l"(gptr))
#define CP_COMMIT() asm volatile("cp.async.commit_group;" ::: "memory")
#define CP_WAIT2()  asm volatile("cp.async.wait_group 2;" ::: "memory")

#define MMA_TF32(d, a, b0, b1)                                                    \
    asm volatile("mma.sync.aligned.m16n8k8.row.col.f32.tf32.tf32.f32 "            \
                 "{%0,%1,%2,%3}, {%4,%5,%6,%7}, {%8,%9}, {%0,%1,%2,%3};"          \
                 : "+f"((d)[0]), "+f"((d)[1]), "+f"((d)[2]), "+f"((d)[3])         \
                 : "r"((a)[0]), "r"((a)[1]), "r"((a)[2]), "r"((a)[3]),            \
                   "r"(b0), "r"(b1))

__device__ __forceinline__ void red_add_v4(float* p, float4 v) {
    asm volatile("red.global.add.v4.f32 [%0], {%1, %2, %3, %4};"
                 :: "l"(p), "f"(v.x), "f"(v.y), "f"(v.z), "f"(v.w) : "memory");
}

// ---------------- fused tensor-core GEMM (mma.sync tf32, 3-stage pipe) ----------------
// acc[128,200] = sum_parts Apart @ Bpart^T; after part0: acc *= 1/max(deg,1).
// mode 0: out = rrelu(acc); optional row-ssq -> ssqout; optional zero zaggp rows.
// mode 1: tw=sigmoid(acc+bt); sc=1/max(sqrt(ssqv[row]),eps);
//         h = tw*(curv*sc) + (1-tw)*h; hist = h.
__global__ void __launch_bounds__(256)
k_mma_gemm(const float* __restrict__ A0, const float* __restrict__ A1,
           const float* __restrict__ B0g, const float* __restrict__ B1g,
           const float* __restrict__ degv, float* __restrict__ outp,
           float* __restrict__ ssqout, float* __restrict__ zaggp,
           const float* __restrict__ bt, const float* __restrict__ curv,
           const float* __restrict__ ssqv,
           float* __restrict__ hstate, float* __restrict__ hist,
           int mode, int nparts) {
    __shared__ __align__(16) float sm[3 * 4032];  // per stage: 1536 A + 2496 B
    __shared__ float s_ssq[128];
    int tid = threadIdx.x, lane = tid & 31, wid = tid >> 5;
    int wr = wid >> 1, wc = wid & 1;
    int row0 = blockIdx.x * 128;
    if (tid < 128) s_ssq[tid] = 0.f;

    float acc[2][13][4];
    #pragma unroll
    for (int mt = 0; mt < 2; ++mt)
        #pragma unroll
        for (int nt = 0; nt < 13; ++nt)
            #pragma unroll
            for (int q = 0; q < 4; ++q) acc[mt][nt][q] = 0.f;

    const int nk = nparts * 25;

    auto issue = [&](int c) {
        if (c < nk) {
            const float* A = (c < 25) ? A0 : A1;
            const float* B = (c < 25) ? B0g : B1g;
            int k0 = ((c < 25) ? c : c - 25) * 8;
            int base = (c % 3) * 4032;
            {
                int r = tid >> 1, h = tid & 1;
                int row = row0 + r;
                if (row >= NN) row = NN - 1;
                CP16(smem_u32(&sm[base + r * 12 + h * 4]),
                     A + (size_t)row * DD + k0 + h * 4);
            }
            #pragma unroll
            for (int j = tid; j < 416; j += 256) {
                int n = j >> 1, h = j & 1;
                CP16(smem_u32(&sm[base + 1536 + n * 12 + h * 4]),
                     B + (size_t)n * DD + k0 + h * 4);
            }
        }
        CP_COMMIT();
    };

    issue(0); issue(1); issue(2);
    for (int c = 0; c < nk; ++c) {
        CP_WAIT2();
        __syncthreads();
        int base = (c % 3) * 4032;
        uint32_t a[2][4];
        int rb = wr * 32 + (lane >> 2);
        int kk = lane & 3;
        #pragma unroll
        for (int mt = 0; mt < 2; ++mt) {
            int r = rb + mt * 16;
            a[mt][0] = __float_as_uint(sm[base + r * 12 + kk]);
            a[mt][1] = __float_as_uint(sm[base + (r + 8) * 12 + kk]);
            a[mt][2] = __float_as_uint(sm[base + r * 12 + kk + 4]);
            a[mt][3] = __float_as_uint(sm[base + (r + 8) * 12 + kk + 4]);
        }
        int nb = wc * 104 + (lane >> 2);
        #pragma unroll
        for (int nt = 0; nt < 13; ++nt) {
            int n = nb + nt * 8;
            uint32_t b0 = __float_as_uint(sm[base + 1536 + n * 12 + kk]);
            uint32_t b1 = __float_as_uint(sm[base + 1536 + n * 12 + kk + 4]);
            MMA_TF32(acc[0][nt], a[0], b0, b1);
            MMA_TF32(acc[1][nt], a[1], b0, b1);
        }
        // end of part 0: apply per-row 1/max(deg,1)
        if (c == 24 && nparts == 2) {
            #pragma unroll
            for (int mt = 0; mt < 2; ++mt) {
                int r = row0 + wr * 32 + mt * 16 + (lane >> 2);
                int r2 = r + 8;
                float n0 = 1.f / fmaxf(degv[r < NN ? r : NN - 1], 1.f);
                float n1 = 1.f / fmaxf(degv[r2 < NN ? r2 : NN - 1], 1.f);
                #pragma unroll
                for (int nt = 0; nt < 13; ++nt) {
                    acc[mt][nt][0] *= n0; acc[mt][nt][1] *= n0;
                    acc[mt][nt][2] *= n1; acc[mt][nt][3] *= n1;
                }
            }
        }
        __syncthreads();
        issue(c + 3);
    }

    // ---- epilogue ----
    float sq[2][2] = {{0.f, 0.f}, {0.f, 0.f}};
    #pragma unroll
    for (int mt = 0; mt < 2; ++mt) {
        int r = row0 + wr * 32 + mt * 16 + (lane >> 2);
        #pragma unroll
        for (int nt = 0; nt < 13; ++nt) {
            int col = wc * 104 + nt * 8 + (lane & 3) * 2;
            if (col >= DD) continue;
            #pragma unroll
            for (int half = 0; half < 2; ++half) {
                int row = r + half * 8;
                if (row >= NN) continue;
                float v0 = acc[mt][nt][half * 2];
                float v1 = acc[mt][nt][half * 2 + 1];
                size_t off = (size_t)row * DD + col;
                if (mode == 0) {
                    float2 o;
                    o.x = (v0 >= 0.f) ? v0 : v0 * SLOPE;
                    o.y = (v1 >= 0.f) ? v1 : v1 * SLOPE;
                    *(float2*)&outp[off] = o;
                    sq[mt][half] += o.x * o.x + o.y * o.y;
                } else {
                    float sc = 1.f / fmaxf(sqrtf(ssqv[row]), 1e-12f);
                    float t0 = 1.f / (1.f + expf(-(v0 + bt[col])));
                    float t1 = 1.f / (1.f + expf(-(v1 + bt[col + 1])));
                    float2 cu = *(const float2*)&curv[off];
                    float2 ho = *(const float2*)&hstate[off];
                    float2 hn;
                    hn.x = t0 * (cu.x * sc) + (1.f - t0) * ho.x;
                    hn.y = t1 * (cu.y * sc) + (1.f - t1) * ho.y;
                    *(float2*)&hstate[off] = hn;
                    *(float2*)&hist[off] = hn;
                }
            }
        }
    }
    if (mode == 0) {
        if (ssqout != nullptr) {
            #pragma unroll
            for (int mt = 0; mt < 2; ++mt)
                #pragma unroll
                for (int half = 0; half < 2; ++half) {
                    float v = sq[mt][half];
                    v += __shfl_xor_sync(0xffffffffu, v, 1);
                    v += __shfl_xor_sync(0xffffffffu, v, 2);
                    if ((lane & 3) == 0)
                        atomicAdd(&s_ssq[wr * 32 + mt * 16 + (lane >> 2) + half * 8], v);
                }
            __syncthreads();
            if (tid < 128 && row0 + tid < NN) ssqout[row0 + tid] = s_ssq[tid];
        }
        if (zaggp != nullptr) {
            float4 z = make_float4(0.f, 0.f, 0.f, 0.f);
            for (int i = tid; i < 128 * 50; i += 256) {
                int r = i / 50, q = i - r * 50;
                int row = row0 + r;
                if (row < NN) ((float4*)&zaggp[(size_t)row * DD])[q] = z;
            }
        }
    }
}

// ---------------- relation CSR + degree (fused) ----------------
__global__ void k_count(const int* __restrict__ dst, const int* __restrict__ et) {
    int e = blockIdx.x * blockDim.x + threadIdx.x;
    if (e < EE) {
        atomicAdd(&g_iblk[et[e]], 2);
        atomicAdd((float*)&g_iblk[2 * RR + dst[e]], 1.f);
    }
}
__global__ void __launch_bounds__(512) k_rscan() {
    __shared__ int s[512];
    int tid = threadIdx.x;
    int v = (tid < RR) ? g_iblk[tid] : 0;
    s[tid] = v;
    __syncthreads();
    for (int o = 1; o < 512; o <<= 1) {
        int u = (tid >= o) ? s[tid - o] : 0;
        __syncthreads();
        s[tid] += u;
        __syncthreads();
    }
    if (tid < RR) g_roff[tid] = s[tid] - v;  // exclusive
    if (tid == 0) g_roff[RR] = 2 * EE;
}
__global__ void k_rfill(const int* __restrict__ src, const int* __restrict__ dst,
                        const int* __restrict__ et) {
    int e = blockIdx.x * blockDim.x + threadIdx.x;
    if (e >= EE) return;
    int r = et[e];
    int pos = g_roff[r] + atomicAdd(&g_iblk[RR + r], 2);
    g_rlist[pos] = src[e];
    g_rlist[pos + 1] = dst[e];
}

// ---------------- GRU fused with relation-mean gather ----------------
__global__ void __launch_bounds__(256)
k_gru(const float* __restrict__ emb_rel, const float* __restrict__ W_ih,
      const float* __restrict__ W_hh, const float* __restrict__ b_ih,
      const float* __restrict__ b_hh) {
    __shared__ float sx[2 * DD];
    __shared__ float shp[DD];
    __shared__ __align__(16) float part[8 * DD];
    __shared__ float sgi[3 * DD];
    __shared__ float sgh[3 * DD];
    __shared__ float shn[DD];
    __shared__ float sred[8];
    int r = blockIdx.x, tid = threadIdx.x, lane = tid & 31, wid = tid >> 5;
    int beg = g_roff[r], end = g_roff[r + 1];

    float4 a0 = make_float4(0.f, 0.f, 0.f, 0.f);
    float4 a1 = a0;
    for (int j = beg + wid; j < end; j += 8) {
        int ent = g_rlist[j];
        const float4* hs = (const float4*)(g_h + (size_t)ent * DD);
        float4 x = hs[lane];
        a0.x += x.x; a0.y += x.y; a0.z += x.z; a0.w += x.w;
        if (lane < 18) {
            float4 u = hs[lane + 32];
            a1.x += u.x; a1.y += u.y; a1.z += u.z; a1.w += u.w;
        }
    }
    float4* pw = (float4*)(part + wid * DD);
    pw[lane] = a0;
    if (lane < 18) pw[lane + 32] = a1;

    for (int d = tid; d < DD; d += 256) {
        sx[d] = emb_rel[r * DD + d];
        shp[d] = g_h0[r * DD + d];
    }
    __syncthreads();
    float inv_cnt = 1.f / fmaxf((float)(end - beg), 1.f);
    for (int d = tid; d < DD; d += 256) {
        float s = 0.f;
        #pragma unroll
        for (int w = 0; w < 8; ++w) s += part[w * DD + d];
        sx[DD + d] = s * inv_cnt;
    }
    __syncthreads();

    for (int j = wid; j < 3 * DD; j += 8) {
        const float* wi = W_ih + (size_t)j * (2 * DD);
        float a = 0.f;
        for (int k = lane; k < 2 * DD; k += 32) a = fmaf(sx[k], wi[k], a);
        const float* wh = W_hh + (size_t)j * DD;
        float b = 0.f;
        for (int k = lane; k < DD; k += 32) b = fmaf(shp[k], wh[k], b);
        #pragma unroll
        for (int o = 16; o; o >>= 1) {
            a += __shfl_xor_sync(0xffffffffu, a, o);
            b += __shfl_xor_sync(0xffffffffu, b, o);
        }
        if (lane == 0) { sgi[j] = a + b_ih[j]; sgh[j] = b + b_hh[j]; }
    }
    __syncthreads();
    float ss = 0.f;
    for (int d = tid; d < DD; d += 256) {
        float rg = 1.f / (1.f + expf(-(sgi[d] + sgh[d])));
        float zg = 1.f / (1.f + expf(-(sgi[DD + d] + sgh[DD + d])));
        float ng = tanhf(sgi[2 * DD + d] + rg * sgh[2 * DD + d]);
        float hn = (1.f - zg) * ng + zg * shp[d];
        shn[d] = hn;
        ss += hn * hn;
    }
    #pragma unroll
    for (int o = 16; o; o >>= 1) ss += __shfl_xor_sync(0xffffffffu, ss, o);
    if (lane == 0) sred[wid] = ss;
    __syncthreads();
    if (tid == 0) {
        float t = 0.f;
        #pragma unroll
        for (int i = 0; i < 8; ++i) t += sred[i];
        sred[0] = t;
    }
    __syncthreads();
    float s = 1.f / fmaxf(sqrtf(sred[0]), 1e-12f);
    for (int d = tid; d < DD; d += 256) g_h0[r * DD + d] = shn[d] * s;
}

// ---------------- edge scatter: agg[dst] += hh[src] + h0[et] ----------------
__global__ void k_edge(const int* __restrict__ src, const int* __restrict__ dst,
                       const int* __restrict__ et, const float* __restrict__ hh) {
    int idx = blockIdx.x * blockDim.x + threadIdx.x;
    if (idx >= EE * 50) return;
    int e = idx / 50, q = idx - e * 50;
    int s = src[e], dn = dst[e], r = et[e];
    float4 a = *(const float4*)&hh[(size_t)s * DD + q * 4];
    float4 b = *(const float4*)&g_h0[(size_t)r * DD + q * 4];
    float4 v = make_float4(a.x + b.x, a.y + b.y, a.z + b.z, a.w + b.w);
    red_add_v4(&g_agg[(size_t)dn * DD + q * 4], v);
}

// ---------------- utility kernels ----------------
__global__ void k_copy(const float* __restrict__ in, float* __restrict__ out, int n) {
    int i = blockIdx.x * blockDim.x + threadIdx.x;
    if (i < n) out[i] = in[i];
}
// transpose 5 weight matrices into g_Bt: [0]=Wn0 [1]=Wl0 [2]=Wn1 [3]=Wl1 [4]=Wt
__global__ void k_transpose_all(const float* __restrict__ Wn, const float* __restrict__ Wl,
                                const float* __restrict__ Wt, float* __restrict__ Bt) {
    int idx = blockIdx.x * blockDim.x + threadIdx.x;
    if (idx >= 5 * DD * DD) return;
    int m = idx / (DD * DD);
    int r = idx - m * (DD * DD);
    int k = r / DD, n = r - k * DD;
    const float* W;
    if (m == 4) W = Wt;
    else if (m & 1) W = Wl + (m >> 1) * DD * DD;
    else W = Wn + (m >> 1) * DD * DD;
    Bt[m * DD * DD + n * DD + k] = W[r];
}
__global__ void k_l2norm_rows(const float* __restrict__ in, float* __restrict__ out, int nrows) {
    int w = (blockIdx.x * blockDim.x + threadIdx.x) >> 5;
    int lane = threadIdx.x & 31;
    if (w >= nrows) return;
    const float* r = in + (size_t)w * DD;
    float ss = 0.f;
    for (int d = lane; d < DD; d += 32) { float v = r[d]; ss += v * v; }
    #pragma unroll
    for (int o = 16; o; o >>= 1) ss += __shfl_xor_sync(0xffffffffu, ss, o);
    float s = 1.f / fmaxf(sqrtf(ss), 1e-12f);
    float* po = out + (size_t)w * DD;
    for (int d = lane; d < DD; d += 32) po[d] = r[d] * s;
}

// ---------------- host driver ----------------
extern "C" void kernel_launch(void* const* d_in, const int* in_sizes, int n_in,
                              void* d_out, int out_size) {
    const int* src = (const int*)d_in[0];
    const int* dst = (const int*)d_in[1];
    const int* et  = (const int*)d_in[2];
    const float* dyn     = (const float*)d_in[3];
    const float* emb_rel = (const float*)d_in[4];
    const float* W_ih    = (const float*)d_in[5];
    const float* W_hh    = (const float*)d_in[6];
    const float* b_ih    = (const float*)d_in[7];
    const float* b_hh    = (const float*)d_in[8];
    const float* W_nb    = (const float*)d_in[9];
    const float* W_lp    = (const float*)d_in[10];
    const float* Wt      = (const float*)d_in[11];
    const float* bt      = (const float*)d_in[12];
    float* out = (float*)d_out;

    float *p_h, *p_hhA, *p_hhB, *p_agg, *p_ssq, *p_h0, *p_Bt;
    int* p_iblk;
    cudaGetSymbolAddress((void**)&p_h,    g_h);
    cudaGetSymbolAddress((void**)&p_hhA,  g_hhA);
    cudaGetSymbolAddress((void**)&p_hhB,  g_hhB);
    cudaGetSymbolAddress((void**)&p_agg,  g_agg);
    cudaGetSymbolAddress((void**)&p_ssq,  g_ssq);
    cudaGetSymbolAddress((void**)&p_h0,   g_h0);
    cudaGetSymbolAddress((void**)&p_Bt,   g_Bt);
    cudaGetSymbolAddress((void**)&p_iblk, g_iblk);
    float* p_deg = (float*)(p_iblk + 2 * RR);

    const int gemm_blocks = (NN + 127) / 128;  // 391
    const int eb = (EE * 50 + 255) / 256;
    const int e1 = (EE + 255) / 256;

    k_transpose_all<<<(5 * DD * DD + 255) / 256, 256>>>(W_nb, W_lp, Wt, p_Bt);
    k_l2norm_rows<<<(NN * 32 + 255) / 256, 256>>>(dyn, p_h, NN);
    k_copy<<<(RR * DD + 255) / 256, 256>>>(emb_rel, p_h0, RR * DD);
    cudaMemsetAsync(p_agg, 0, (size_t)NN * DD * sizeof(float));

    for (int t = 0; t < TT; ++t) {
        const int* s_t = src + t * EE;
        const int* d_t = dst + t * EE;
        const int* e_t = et  + t * EE;

        // counts (relation + degree), CSR, GRU
        cudaMemsetAsync(p_iblk, 0, (2 * RR + NN) * sizeof(int));
        k_count<<<e1, 256>>>(d_t, e_t);
        k_rscan<<<1, 512>>>();
        k_rfill<<<e1, 256>>>(s_t, d_t, e_t);
        k_gru<<<RR, 256>>>(emb_rel, W_ih, W_hh, b_ih, b_hh);

        // layer 0: h -> hhA (epilogue zeroes agg for layer 1)
        k_edge<<<eb, 256>>>(s_t, d_t, e_t, p_h);
        k_mma_gemm<<<gemm_blocks, 256>>>(
            p_agg, p_h, p_Bt + 0 * DD * DD, p_Bt + 1 * DD * DD, p_deg,
            p_hhA, nullptr, p_agg, nullptr, nullptr, nullptr, nullptr, nullptr, 0, 2);

        // layer 1: hhA -> hhB (+ row ssq; epilogue zeroes agg for next step)
        k_edge<<<eb, 256>>>(s_t, d_t, e_t, p_hhA);
        k_mma_gemm<<<gemm_blocks, 256>>>(
            p_agg, p_hhA, p_Bt + 2 * DD * DD, p_Bt + 3 * DD * DD, p_deg,
            p_hhB, p_ssq, p_agg, nullptr, nullptr, nullptr, nullptr, nullptr, 0, 2);

        // time gate: h = sigmoid(h@Wt+bt)*(hhB*rsqrt(ssq)) + (1-..)*h; hist = h
        k_mma_gemm<<<gemm_blocks, 256>>>(
            p_h, nullptr, p_Bt + 4 * DD * DD, nullptr, nullptr,
            nullptr, nullptr, nullptr, bt, p_hhB, p_ssq, p_h,
            out + (size_t)t * NN * DD, 1, 1);
    }
}